// round 1
// baseline (speedup 1.0000x reference)
#include <cuda_runtime.h>

constexpr int   KIN   = 128;   // IN_CH
constexpr int   HC    = 64;    // HEADS * OUT_CH
constexpr float SLOPE = 0.2f;
constexpr int   MAXN  = 50176;
constexpr int   MAXE  = 800000;
constexpr int   MAXADJ = MAXE + MAXN;
#define FULLMASK 0xffffffffu

// ---------------- scratch (static device globals; no allocations) ----------------
__device__ float  g_h[(size_t)MAXN * HC];   // projected features [N][64]
__device__ float2 g_as[MAXN];               // alpha_src per node (head0, head1)
__device__ float2 g_ad[MAXN];               // alpha_dst per node
__device__ int    g_deg[MAXN];
__device__ int    g_rowptr[MAXN + 1];
__device__ int    g_cursor[MAXN];
__device__ int    g_adj[MAXADJ];            // CSR by dst: stores src node id
__device__ int    g_bsum[256];
__device__ int    g_boff[256];
__device__ int    g_is64;

// ---------------- edge-index dtype detection (int64 vs int32) ----------------
// If int64: odd 32-bit words are high halves of values < 2^31 -> all zero.
// If int32: odd words are random node ids in [0, 50000) -> essentially never all zero.
__global__ void detect_kernel(const int* __restrict__ ei32)
{
    __shared__ int nz;
    if (threadIdx.x == 0) nz = 0;
    __syncthreads();
    int v = ei32[2 * threadIdx.x + 1];
    if (v != 0) atomicOr(&nz, 1);
    __syncthreads();
    if (threadIdx.x == 0) g_is64 = (nz == 0) ? 1 : 0;
}

__device__ __forceinline__ int eidx(const void* ei, int i)
{
    return g_is64 ? (int)((const long long*)ei)[i] : ((const int*)ei)[i];
}

// ---------------- GEMM: h = x @ W  (64-row tile, x staged+transposed in smem, W via L1) ----------------
__global__ void gemm_kernel(const float* __restrict__ x, const float* __restrict__ W, int n)
{
    __shared__ float xs[KIN][64];     // xs[k][r], 32 KB
    int tid  = threadIdx.x;           // 256 threads
    int row0 = blockIdx.x * 64;

    // load x tile transposed; warp lanes map to consecutive rows -> conflict-free STS
    int r   = tid & 63;
    int kq  = tid >> 6;               // k quarter (32 k's each)
    int row = row0 + r;
    const float* xrow = x + (size_t)row * KIN + kq * 32;
#pragma unroll
    for (int j = 0; j < 8; ++j) {
        float4 v = make_float4(0.f, 0.f, 0.f, 0.f);
        if (row < n) v = *(const float4*)(xrow + j * 4);
        int k = kq * 32 + j * 4;
        xs[k + 0][r] = v.x; xs[k + 1][r] = v.y;
        xs[k + 2][r] = v.z; xs[k + 3][r] = v.w;
    }
    __syncthreads();

    int tr = (tid >> 4) << 2;         // row offset within tile
    int tc = (tid & 15) << 2;         // col offset
    float acc[4][4];
#pragma unroll
    for (int i = 0; i < 4; ++i)
#pragma unroll
        for (int j = 0; j < 4; ++j) acc[i][j] = 0.f;

#pragma unroll 8
    for (int k = 0; k < KIN; ++k) {
        float4 xv = *(const float4*)&xs[k][tr];
        float4 wv = __ldg((const float4*)(W + k * HC + tc));   // W (32 KB) lives in L1
        acc[0][0] = fmaf(xv.x, wv.x, acc[0][0]);
        acc[0][1] = fmaf(xv.x, wv.y, acc[0][1]);
        acc[0][2] = fmaf(xv.x, wv.z, acc[0][2]);
        acc[0][3] = fmaf(xv.x, wv.w, acc[0][3]);
        acc[1][0] = fmaf(xv.y, wv.x, acc[1][0]);
        acc[1][1] = fmaf(xv.y, wv.y, acc[1][1]);
        acc[1][2] = fmaf(xv.y, wv.z, acc[1][2]);
        acc[1][3] = fmaf(xv.y, wv.w, acc[1][3]);
        acc[2][0] = fmaf(xv.z, wv.x, acc[2][0]);
        acc[2][1] = fmaf(xv.z, wv.y, acc[2][1]);
        acc[2][2] = fmaf(xv.z, wv.z, acc[2][2]);
        acc[2][3] = fmaf(xv.z, wv.w, acc[2][3]);
        acc[3][0] = fmaf(xv.w, wv.x, acc[3][0]);
        acc[3][1] = fmaf(xv.w, wv.y, acc[3][1]);
        acc[3][2] = fmaf(xv.w, wv.z, acc[3][2]);
        acc[3][3] = fmaf(xv.w, wv.w, acc[3][3]);
    }
#pragma unroll
    for (int i = 0; i < 4; ++i) {
        int rr = row0 + tr + i;
        if (rr < n)
            *(float4*)(g_h + (size_t)rr * HC + tc) =
                make_float4(acc[i][0], acc[i][1], acc[i][2], acc[i][3]);
    }
}

// ---------------- per-node attention logits: alpha_s/alpha_d ----------------
__global__ void alpha_kernel(const float* __restrict__ a_src, const float* __restrict__ a_dst, int n)
{
    int i = blockIdx.x * blockDim.x + threadIdx.x;
    if (i >= n) return;
    const float4* hv = (const float4*)(g_h + (size_t)i * HC);
    float s0 = 0.f, d0 = 0.f, s1 = 0.f, d1 = 0.f;
#pragma unroll
    for (int j = 0; j < 8; ++j) {            // head 0 channels
        float4 h4 = hv[j];
        float4 a4 = __ldg((const float4*)a_src + j);
        float4 b4 = __ldg((const float4*)a_dst + j);
        s0 = fmaf(h4.x, a4.x, s0); s0 = fmaf(h4.y, a4.y, s0);
        s0 = fmaf(h4.z, a4.z, s0); s0 = fmaf(h4.w, a4.w, s0);
        d0 = fmaf(h4.x, b4.x, d0); d0 = fmaf(h4.y, b4.y, d0);
        d0 = fmaf(h4.z, b4.z, d0); d0 = fmaf(h4.w, b4.w, d0);
    }
#pragma unroll
    for (int j = 8; j < 16; ++j) {           // head 1 channels
        float4 h4 = hv[j];
        float4 a4 = __ldg((const float4*)a_src + j);
        float4 b4 = __ldg((const float4*)a_dst + j);
        s1 = fmaf(h4.x, a4.x, s1); s1 = fmaf(h4.y, a4.y, s1);
        s1 = fmaf(h4.z, a4.z, s1); s1 = fmaf(h4.w, a4.w, s1);
        d1 = fmaf(h4.x, b4.x, d1); d1 = fmaf(h4.y, b4.y, d1);
        d1 = fmaf(h4.z, b4.z, d1); d1 = fmaf(h4.w, b4.w, d1);
    }
    g_as[i] = make_float2(s0, s1);
    g_ad[i] = make_float2(d0, d1);
}

// ---------------- CSR build ----------------
__global__ void zero_kernel(int n)
{
    int i = blockIdx.x * blockDim.x + threadIdx.x;
    if (i < n) g_deg[i] = 0;
}

__global__ void count_kernel(const void* __restrict__ ei, int e)
{
    int i = blockIdx.x * blockDim.x + threadIdx.x;
    if (i < e) atomicAdd(&g_deg[eidx(ei, e + i)], 1);
}

__global__ void scan1_kernel(int n)
{
    __shared__ int sh[1024];
    int tid = threadIdx.x;
    int i = blockIdx.x * 1024 + tid;
    int v = (i < n) ? (g_deg[i] + 1) : 0;      // +1 = self loop
    sh[tid] = v;
    __syncthreads();
    for (int o = 1; o < 1024; o <<= 1) {
        int t = (tid >= o) ? sh[tid - o] : 0;
        __syncthreads();
        sh[tid] += t;
        __syncthreads();
    }
    if (i < n) g_rowptr[i] = sh[tid] - v;      // exclusive within chunk
    if (tid == 1023) g_bsum[blockIdx.x] = sh[1023];
}

__global__ void scan2_kernel(int nb)
{
    __shared__ int sh[256];
    int tid = threadIdx.x;
    int v = (tid < nb) ? g_bsum[tid] : 0;
    sh[tid] = v;
    __syncthreads();
    for (int o = 1; o < 256; o <<= 1) {
        int t = (tid >= o) ? sh[tid - o] : 0;
        __syncthreads();
        sh[tid] += t;
        __syncthreads();
    }
    g_boff[tid] = sh[tid] - v;                 // exclusive chunk offsets
}

__global__ void scan3_kernel(int n, int total)
{
    int i = blockIdx.x * 1024 + threadIdx.x;
    if (i < n) {
        int rp = g_rowptr[i] + g_boff[blockIdx.x];
        g_rowptr[i] = rp;
        g_cursor[i] = rp;
    }
    if (i == 0) g_rowptr[n] = total;
}

__global__ void fill_kernel(const void* __restrict__ ei, int e, int n)
{
    int i = blockIdx.x * blockDim.x + threadIdx.x;
    if (i < e) {
        int s = eidx(ei, i);
        int d = eidx(ei, e + i);
        int p = atomicAdd(&g_cursor[d], 1);
        g_adj[p] = s;
    } else if (i < e + n) {
        int v = i - e;                          // self loop
        int p = atomicAdd(&g_cursor[v], 1);
        g_adj[p] = v;
    }
}

// ---------------- aggregation: one warp per dst node, online softmax, no atomics ----------------
// Lane L owns output channels {2L, 2L+1}; head = L/16 (channels 0..31 head0, 32..63 head1).
__global__ void aggregate_kernel(const float* __restrict__ bias, float* __restrict__ out, int n)
{
    int gw   = (blockIdx.x * blockDim.x + threadIdx.x) >> 5;
    int lane = threadIdx.x & 31;
    if (gw >= n) return;

    int beg = g_rowptr[gw];
    int end = g_rowptr[gw + 1];
    float2 adn = g_ad[gw];
    int head = lane >> 4;

    float m0 = -1e30f, m1 = -1e30f;   // running maxes (warp-uniform), per head
    float s  = 0.f;                    // running sum for *my* head
    float2 acc = make_float2(0.f, 0.f);
    const float* hb = g_h + (lane << 1);

    for (int cs = beg; cs < end; cs += 32) {
        int j = cs + lane;
        int srcj = 0;
        float e0 = -1e30f, e1 = -1e30f;
        if (j < end) {
            srcj = g_adj[j];
            float2 a = g_as[srcj];
            e0 = a.x + adn.x; e0 = (e0 > 0.f) ? e0 : SLOPE * e0;
            e1 = a.y + adn.y; e1 = (e1 > 0.f) ? e1 : SLOPE * e1;
        }
        // warp max per head
        float c0 = e0, c1 = e1;
#pragma unroll
        for (int o = 16; o; o >>= 1) {
            c0 = fmaxf(c0, __shfl_xor_sync(FULLMASK, c0, o));
            c1 = fmaxf(c1, __shfl_xor_sync(FULLMASK, c1, o));
        }
        float nm0 = fmaxf(m0, c0), nm1 = fmaxf(m1, c1);
        float sc = __expf(head ? (m1 - nm1) : (m0 - nm0));
        acc.x *= sc; acc.y *= sc; s *= sc;
        float w0 = __expf(e0 - nm0);   // 0 for invalid lanes
        float w1 = __expf(e1 - nm1);
        m0 = nm0; m1 = nm1;
        // warp sum per head
        float t0 = w0, t1 = w1;
#pragma unroll
        for (int o = 16; o; o >>= 1) {
            t0 += __shfl_xor_sync(FULLMASK, t0, o);
            t1 += __shfl_xor_sync(FULLMASK, t1, o);
        }
        s += head ? t1 : t0;

        int cnt = min(32, end - cs);
        for (int t = 0; t < cnt; ++t) {
            int   st = __shfl_sync(FULLMASK, srcj, t);
            float a0 = __shfl_sync(FULLMASK, w0, t);
            float a1 = __shfl_sync(FULLMASK, w1, t);
            float wt = head ? a1 : a0;
            float2 hv = *(const float2*)(hb + (size_t)st * HC);  // coalesced 256B/warp
            acc.x = fmaf(wt, hv.x, acc.x);
            acc.y = fmaf(wt, hv.y, acc.y);
        }
    }
    float inv = 1.f / (s + 1e-16f);
    float bx = bias[lane << 1];
    float by = bias[(lane << 1) + 1];
    *(float2*)(out + (size_t)gw * HC + (lane << 1)) =
        make_float2(acc.x * inv + bx, acc.y * inv + by);
}

// ---------------- launch ----------------
extern "C" void kernel_launch(void* const* d_in, const int* in_sizes, int n_in,
                              void* d_out, int out_size)
{
    const float* x     = (const float*)d_in[0];
    const void*  ei    = d_in[1];
    const float* W     = (const float*)d_in[2];
    const float* a_src = (const float*)d_in[3];
    const float* a_dst = (const float*)d_in[4];
    const float* bias  = (const float*)d_in[5];
    float* out = (float*)d_out;

    int n  = in_sizes[0] / KIN;
    int e  = in_sizes[1] / 2;
    int nB = (n + 1023) / 1024;
    int total = e + n;

    detect_kernel<<<1, 1024>>>((const int*)ei);
    zero_kernel<<<(n + 255) / 256, 256>>>(n);
    count_kernel<<<(e + 255) / 256, 256>>>(ei, e);
    scan1_kernel<<<nB, 1024>>>(n);
    scan2_kernel<<<1, 256>>>(nB);
    scan3_kernel<<<nB, 1024>>>(n, total);
    fill_kernel<<<(total + 255) / 256, 256>>>(ei, e, n);
    gemm_kernel<<<(n + 63) / 64, 256>>>(x, W, n);
    alpha_kernel<<<(n + 255) / 256, 256>>>(a_src, a_dst, n);
    aggregate_kernel<<<(n + 7) / 8, 256>>>(bias, out, n);
}

// round 3
// speedup vs baseline: 1.0949x; 1.0949x over previous
#include <cuda_runtime.h>

constexpr int   KIN   = 128;   // IN_CH
constexpr int   HC    = 64;    // HEADS * OUT_CH
constexpr float SLOPE = 0.2f;
constexpr int   MAXN  = 50176;
constexpr int   MAXE  = 800000;
constexpr int   MAXADJ = MAXE + MAXN;
#define FULLMASK 0xffffffffu

// ---------------- scratch (static device globals; no allocations) ----------------
__device__ float  g_h[(size_t)MAXN * HC];   // projected features [N][64]
__device__ float2 g_as[MAXN];               // alpha_src per node (head0, head1)
__device__ float2 g_ad[MAXN];               // alpha_dst per node
__device__ int    g_deg[MAXN];
__device__ int    g_rowptr[MAXN + 1];
__device__ int    g_cursor[MAXN];
__device__ int    g_adj[MAXADJ];            // CSR by dst: stores src node id
__device__ int    g_bsum[256];
__device__ int    g_is64;

// ---------------- init: zero degrees + detect edge-index dtype (int64 vs int32) ----
// int64 edge values < 2^31 -> all odd 32-bit words zero; int32 -> random ids.
__global__ void init_kernel(const int* __restrict__ ei32, int n)
{
    int i = blockIdx.x * 1024 + threadIdx.x;
    if (i < n) g_deg[i] = 0;

    if (blockIdx.x == 0) {
        __shared__ int nz;
        if (threadIdx.x == 0) nz = 0;
        __syncthreads();
        if (ei32[2 * threadIdx.x + 1] != 0) atomicOr(&nz, 1);
        __syncthreads();
        if (threadIdx.x == 0) g_is64 = (nz == 0) ? 1 : 0;
    }
}

__device__ __forceinline__ int eidx(const void* ei, int i)
{
    return g_is64 ? (int)((const long long*)ei)[i] : ((const int*)ei)[i];
}

// ---------------- CSR build ----------------
__global__ void count_kernel(const void* __restrict__ ei, int e)
{
    int i = blockIdx.x * blockDim.x + threadIdx.x;
    if (i < e) atomicAdd(&g_deg[eidx(ei, e + i)], 1);
}

// block-local exclusive scan of (deg+1), warp-shuffle based (2 barriers)
__global__ void scan1_kernel(int n)
{
    __shared__ int ws[32];
    int tid = threadIdx.x, lane = tid & 31, wid = tid >> 5;
    int i = blockIdx.x * 1024 + tid;
    int v = (i < n) ? (g_deg[i] + 1) : 0;       // +1 = self loop
    int x = v;
#pragma unroll
    for (int o = 1; o < 32; o <<= 1) {
        int t = __shfl_up_sync(FULLMASK, x, o);
        if (lane >= o) x += t;
    }
    if (lane == 31) ws[wid] = x;
    __syncthreads();
    if (wid == 0) {
        int y = ws[lane];
#pragma unroll
        for (int o = 1; o < 32; o <<= 1) {
            int t = __shfl_up_sync(FULLMASK, y, o);
            if (lane >= o) y += t;
        }
        ws[lane] = y;
    }
    __syncthreads();
    int excl = x - v + (wid ? ws[wid - 1] : 0);
    if (i < n) g_rowptr[i] = excl;
    if (tid == 1023) g_bsum[blockIdx.x] = ws[31];
}

// finalize rowptr: each block sums g_bsum[0..blockIdx.x) itself (<=49 ints)
__global__ void scan3_kernel(int n, int total)
{
    __shared__ int off;
    if (threadIdx.x < 32) {
        int v = 0;
        for (int b = threadIdx.x; b < blockIdx.x; b += 32) v += g_bsum[b];
#pragma unroll
        for (int o = 16; o; o >>= 1) v += __shfl_xor_sync(FULLMASK, v, o);
        if (threadIdx.x == 0) off = v;
    }
    __syncthreads();
    int i = blockIdx.x * 1024 + threadIdx.x;
    if (i < n) {
        int rp = g_rowptr[i] + off;
        g_rowptr[i] = rp;
        g_cursor[i] = rp;
    }
    if (i == 0) g_rowptr[n] = total;
}

__global__ void fill_kernel(const void* __restrict__ ei, int e, int n)
{
    int i = blockIdx.x * blockDim.x + threadIdx.x;
    if (i < e) {
        int s = eidx(ei, i);
        int d = eidx(ei, e + i);
        int p = atomicAdd(&g_cursor[d], 1);
        g_adj[p] = s;
    } else if (i < e + n) {
        int v = i - e;                          // self loop
        int p = atomicAdd(&g_cursor[v], 1);
        g_adj[p] = v;
    }
}

// ---------------- GEMM h = x@W + fused per-node attention logits ----------------
__global__ void gemm_alpha_kernel(const float* __restrict__ x, const float* __restrict__ W,
                                  const float* __restrict__ a_src, const float* __restrict__ a_dst,
                                  int n)
{
    __shared__ float xs[KIN][64];     // 32 KB; reused as 64x65 output tile in epilogue
    int tid  = threadIdx.x;           // 256 threads
    int row0 = blockIdx.x * 64;

    // stage x tile transposed (conflict-free: lanes -> consecutive rows)
    int r   = tid & 63;
    int kq  = tid >> 6;
    int row = row0 + r;
    const float* xrow = x + (size_t)row * KIN + kq * 32;
#pragma unroll
    for (int j = 0; j < 8; ++j) {
        float4 v = make_float4(0.f, 0.f, 0.f, 0.f);
        if (row < n) v = *(const float4*)(xrow + j * 4);
        int k = kq * 32 + j * 4;
        xs[k + 0][r] = v.x; xs[k + 1][r] = v.y;
        xs[k + 2][r] = v.z; xs[k + 3][r] = v.w;
    }
    __syncthreads();

    int tr = (tid >> 4) << 2;
    int tc = (tid & 15) << 2;
    float acc[4][4];
#pragma unroll
    for (int i = 0; i < 4; ++i)
#pragma unroll
        for (int j = 0; j < 4; ++j) acc[i][j] = 0.f;

#pragma unroll 8
    for (int k = 0; k < KIN; ++k) {
        float4 xv = *(const float4*)&xs[k][tr];
        float4 wv = __ldg((const float4*)(W + k * HC + tc));   // W (32 KB) lives in L1
        acc[0][0] = fmaf(xv.x, wv.x, acc[0][0]);
        acc[0][1] = fmaf(xv.x, wv.y, acc[0][1]);
        acc[0][2] = fmaf(xv.x, wv.z, acc[0][2]);
        acc[0][3] = fmaf(xv.x, wv.w, acc[0][3]);
        acc[1][0] = fmaf(xv.y, wv.x, acc[1][0]);
        acc[1][1] = fmaf(xv.y, wv.y, acc[1][1]);
        acc[1][2] = fmaf(xv.y, wv.z, acc[1][2]);
        acc[1][3] = fmaf(xv.y, wv.w, acc[1][3]);
        acc[2][0] = fmaf(xv.z, wv.x, acc[2][0]);
        acc[2][1] = fmaf(xv.z, wv.y, acc[2][1]);
        acc[2][2] = fmaf(xv.z, wv.z, acc[2][2]);
        acc[2][3] = fmaf(xv.z, wv.w, acc[2][3]);
        acc[3][0] = fmaf(xv.w, wv.x, acc[3][0]);
        acc[3][1] = fmaf(xv.w, wv.y, acc[3][1]);
        acc[3][2] = fmaf(xv.w, wv.z, acc[3][2]);
        acc[3][3] = fmaf(xv.w, wv.w, acc[3][3]);
    }

    // write h to global
#pragma unroll
    for (int i = 0; i < 4; ++i) {
        int rr = row0 + tr + i;
        if (rr < n)
            *(float4*)(g_h + (size_t)rr * HC + tc) =
                make_float4(acc[i][0], acc[i][1], acc[i][2], acc[i][3]);
    }

    // epilogue: alpha dots from the on-chip tile (reuse xs as [64][65])
    __syncthreads();
    float (*tile)[65] = (float (*)[65])xs;
#pragma unroll
    for (int i = 0; i < 4; ++i) {
        tile[tr + i][tc + 0] = acc[i][0];
        tile[tr + i][tc + 1] = acc[i][1];
        tile[tr + i][tc + 2] = acc[i][2];
        tile[tr + i][tc + 3] = acc[i][3];
    }
    __syncthreads();
    if (tid < 64) {
        int rr = row0 + tid;
        if (rr < n) {
            const float* trow = tile[tid];
            float s0 = 0.f, d0 = 0.f, s1 = 0.f, d1 = 0.f;
#pragma unroll
            for (int c = 0; c < 32; ++c) {
                float h = trow[c];
                s0 = fmaf(h, __ldg(a_src + c), s0);
                d0 = fmaf(h, __ldg(a_dst + c), d0);
            }
#pragma unroll
            for (int c = 32; c < 64; ++c) {
                float h = trow[c];
                s1 = fmaf(h, __ldg(a_src + c), s1);
                d1 = fmaf(h, __ldg(a_dst + c), d1);
            }
            g_as[rr] = make_float2(s0, s1);
            g_ad[rr] = make_float2(d0, d1);
        }
    }
}

// ---------------- aggregation: warp per dst node, no-max softmax, no atomics ------
// Lane L owns channels {2L, 2L+1}; head = L/16.
__global__ void aggregate_kernel(const float* __restrict__ bias, float* __restrict__ out, int n)
{
    int gw   = (blockIdx.x * blockDim.x + threadIdx.x) >> 5;
    int lane = threadIdx.x & 31;
    if (gw >= n) return;

    int beg = g_rowptr[gw];
    int end = g_rowptr[gw + 1];
    float2 adn = g_ad[gw];
    int head = lane >> 4;

    float s0 = 0.f, s1 = 0.f;                 // lane-partial denominators
    float2 acc = make_float2(0.f, 0.f);
    const float* hb = g_h + (lane << 1);

    for (int cs = beg; cs < end; cs += 32) {
        int j = cs + lane;
        int srcj = 0;
        float w0 = 0.f, w1 = 0.f;
        if (j < end) {
            srcj = g_adj[j];
            float2 a = g_as[srcj];
            float e0 = a.x + adn.x; e0 = (e0 > 0.f) ? e0 : SLOPE * e0;
            float e1 = a.y + adn.y; e1 = (e1 > 0.f) ? e1 : SLOPE * e1;
            w0 = __expf(e0); w1 = __expf(e1); // logits bounded ~|10| -> safe in fp32
            s0 += w0; s1 += w1;
        }
        int cnt = min(32, end - cs);
        for (int t = 0; t < cnt; ++t) {
            int   st = __shfl_sync(FULLMASK, srcj, t);
            float a0 = __shfl_sync(FULLMASK, w0, t);
            float a1 = __shfl_sync(FULLMASK, w1, t);
            float wt = head ? a1 : a0;
            float2 hv = *(const float2*)(hb + (size_t)st * HC);  // coalesced 256B/warp
            acc.x = fmaf(wt, hv.x, acc.x);
            acc.y = fmaf(wt, hv.y, acc.y);
        }
    }
#pragma unroll
    for (int o = 16; o; o >>= 1) {
        s0 += __shfl_xor_sync(FULLMASK, s0, o);
        s1 += __shfl_xor_sync(FULLMASK, s1, o);
    }
    float s   = head ? s1 : s0;
    float inv = 1.f / (s + 1e-16f);
    float bx = bias[lane << 1];
    float by = bias[(lane << 1) + 1];
    *(float2*)(out + (size_t)gw * HC + (lane << 1)) =
        make_float2(acc.x * inv + bx, acc.y * inv + by);
}

// ---------------- launch ----------------
extern "C" void kernel_launch(void* const* d_in, const int* in_sizes, int n_in,
                              void* d_out, int out_size)
{
    const float* x     = (const float*)d_in[0];
    const void*  ei    = d_in[1];
    const float* W     = (const float*)d_in[2];
    const float* a_src = (const float*)d_in[3];
    const float* a_dst = (const float*)d_in[4];
    const float* bias  = (const float*)d_in[5];
    float* out = (float*)d_out;

    int n  = in_sizes[0] / KIN;
    int e  = in_sizes[1] / 2;
    int nB = (n + 1023) / 1024;
    int total = e + n;

    init_kernel<<<nB, 1024>>>((const int*)ei, n);
    count_kernel<<<(e + 255) / 256, 256>>>(ei, e);
    scan1_kernel<<<nB, 1024>>>(n);
    scan3_kernel<<<nB, 1024>>>(n, total);
    fill_kernel<<<(total + 255) / 256, 256>>>(ei, e, n);
    gemm_alpha_kernel<<<(n + 63) / 64, 256>>>(x, W, a_src, a_dst, n);
    aggregate_kernel<<<(n + 7) / 8, 256>>>(bias, out, n);
}